// round 4
// baseline (speedup 1.0000x reference)
#include <cuda_runtime.h>
#include <cstdint>

// Problem constants (fixed by the dataset).
#define U_C  100000
#define I_C  50000
#define N_C  150000          // U_C + I_C
#define EG_C 2400000
#define EU_C 1600000
#define EI_C 800000
#define ROWS_TOT (N_C + U_C + I_C)     // 300000
#define E_TOT    (EG_C + EU_C + EI_C)  // 4800000

#define TPB 256
#define D64 64

// Output layout (fp32):
//   [0, U*64)              user_emb1 = all_emb1[:U]
//   [U*64, N*64)           item_emb1 = all_emb1[U:]
//   [N*64, (N+U)*64)       user_emb2
//   [(N+U)*64, (N+U+I)*64) item_emb2

// Scratch (static device globals; no allocation).
// Row-space concatenation: graph rows [0,N), user rows [N, N+U), item rows [N+U, N+U+I).
__device__ int  d_counts[ROWS_TOT];
__device__ int  d_offs  [ROWS_TOT];
__device__ int  d_curs  [ROWS_TOT];
__device__ int2 d_perm  [E_TOT];     // {col, float_bits(val)} bucketed by dest row

// ---------------- build passes ----------------

// Histogram over all 3 edge lists (counts region is tiny -> fusion safe).
__global__ void __launch_bounds__(TPB) hist_all(const int* __restrict__ gr,
                                                const int* __restrict__ ur,
                                                const int* __restrict__ ir,
                                                int EG, int EU, int EI, int N_, int U_) {
    int e = blockIdx.x * TPB + threadIdx.x;
    int ET = EG + EU + EI;
    if (e >= ET) return;
    int key;
    if (e < EG)            key = gr[e];
    else if (e < EG + EU)  key = N_ + ur[e - EG];
    else                   key = N_ + U_ + ir[e - EG - EU];
    atomicAdd(&d_counts[key], 1);
}

// Exclusive scan, one block per segment (0:graph N, 1:user U, 2:item I).
__global__ void __launch_bounds__(1024) scan_seg(int N_, int U_, int I_) {
    int base, n;
    if (blockIdx.x == 0)      { base = 0;        n = N_; }
    else if (blockIdx.x == 1) { base = N_;       n = U_; }
    else                      { base = N_ + U_;  n = I_; }

    const int T = 1024;
    int t = threadIdx.x;
    int chunk = (n + T - 1) / T;
    int lo = min(t * chunk, n);
    int hi = min(lo + chunk, n);

    int sum = 0;
    for (int i = lo; i < hi; i++) sum += d_counts[base + i];

    __shared__ int sh[1024];
    sh[t] = sum;
    __syncthreads();
    #pragma unroll
    for (int dstep = 1; dstep < 1024; dstep <<= 1) {
        int v = (t >= dstep) ? sh[t - dstep] : 0;
        __syncthreads();
        sh[t] += v;
        __syncthreads();
    }
    int run = sh[t] - sum;  // exclusive prefix of this thread's chunk
    for (int i = lo; i < hi; i++) {
        d_offs[base + i] = run;
        d_curs[base + i] = run;
        run += d_counts[base + i];
    }
}

// Scatter edges into row-bucketed perm array. Perm index space is per-segment
// (graph perm at 0, user perm at EG, item perm at EG+EU) because each
// segment's cursors start at its own exclusive scan; add segment base.
__global__ void __launch_bounds__(TPB) scatter_all(const int* __restrict__ gr, const int* __restrict__ gc, const float* __restrict__ gv,
                                                   const int* __restrict__ ur, const int* __restrict__ uc, const float* __restrict__ uv,
                                                   const int* __restrict__ ir, const int* __restrict__ ic, const float* __restrict__ iv,
                                                   int EG, int EU, int EI, int N_, int U_) {
    int e = blockIdx.x * TPB + threadIdx.x;
    int ET = EG + EU + EI;
    if (e >= ET) return;
    int key, c; float v; int pbase;
    if (e < EG) {
        key = gr[e];               c = gc[e];            v = gv[e];            pbase = 0;
    } else if (e < EG + EU) {
        int k = e - EG;
        key = N_ + ur[k];          c = uc[k];            v = uv[k];            pbase = EG;
    } else {
        int k = e - EG - EU;
        key = N_ + U_ + ir[k];     c = ic[k];            v = iv[k];            pbase = EG + EU;
    }
    int pos = atomicAdd(&d_curs[key], 1);
    d_perm[pbase + pos] = make_int2(c, __float_as_int(v));
}

// ---------------- main CSR SpMM ----------------
// 16 threads per destination row; register accumulation; one STG.128 per slice.
__global__ void __launch_bounds__(TPB) csr_spmm(const float* __restrict__ src0,
                                                const float* __restrict__ src1,
                                                float* __restrict__ dst,
                                                int n_rows, int U_split,
                                                int row_base, int perm_base) {
    int tid = blockIdx.x * TPB + threadIdx.x;
    int r    = tid >> 4;
    int lane = tid & 15;
    if (r >= n_rows) return;

    int start = d_offs[row_base + r] + perm_base;
    int deg   = d_counts[row_base + r];

    float4 acc = make_float4(0.f, 0.f, 0.f, 0.f);

    int j = 0;
    for (; j + 4 <= deg; j += 4) {
        int2 e0 = d_perm[start + j];
        int2 e1 = d_perm[start + j + 1];
        int2 e2 = d_perm[start + j + 2];
        int2 e3 = d_perm[start + j + 3];
        const float* p0 = (e0.x < U_split) ? src0 + (long long)e0.x * D64 : src1 + (long long)(e0.x - U_split) * D64;
        const float* p1 = (e1.x < U_split) ? src0 + (long long)e1.x * D64 : src1 + (long long)(e1.x - U_split) * D64;
        const float* p2 = (e2.x < U_split) ? src0 + (long long)e2.x * D64 : src1 + (long long)(e2.x - U_split) * D64;
        const float* p3 = (e3.x < U_split) ? src0 + (long long)e3.x * D64 : src1 + (long long)(e3.x - U_split) * D64;
        float4 x0 = reinterpret_cast<const float4*>(p0)[lane];
        float4 x1 = reinterpret_cast<const float4*>(p1)[lane];
        float4 x2 = reinterpret_cast<const float4*>(p2)[lane];
        float4 x3 = reinterpret_cast<const float4*>(p3)[lane];
        float v0 = __int_as_float(e0.y), v1 = __int_as_float(e1.y);
        float v2 = __int_as_float(e2.y), v3 = __int_as_float(e3.y);
        acc.x = fmaf(v0, x0.x, acc.x); acc.y = fmaf(v0, x0.y, acc.y); acc.z = fmaf(v0, x0.z, acc.z); acc.w = fmaf(v0, x0.w, acc.w);
        acc.x = fmaf(v1, x1.x, acc.x); acc.y = fmaf(v1, x1.y, acc.y); acc.z = fmaf(v1, x1.z, acc.z); acc.w = fmaf(v1, x1.w, acc.w);
        acc.x = fmaf(v2, x2.x, acc.x); acc.y = fmaf(v2, x2.y, acc.y); acc.z = fmaf(v2, x2.z, acc.z); acc.w = fmaf(v2, x2.w, acc.w);
        acc.x = fmaf(v3, x3.x, acc.x); acc.y = fmaf(v3, x3.y, acc.y); acc.z = fmaf(v3, x3.z, acc.z); acc.w = fmaf(v3, x3.w, acc.w);
    }
    for (; j < deg; j++) {
        int2 e = d_perm[start + j];
        const float* p = (e.x < U_split) ? src0 + (long long)e.x * D64 : src1 + (long long)(e.x - U_split) * D64;
        float4 x = reinterpret_cast<const float4*>(p)[lane];
        float v = __int_as_float(e.y);
        acc.x = fmaf(v, x.x, acc.x); acc.y = fmaf(v, x.y, acc.y);
        acc.z = fmaf(v, x.z, acc.z); acc.w = fmaf(v, x.w, acc.w);
    }

    reinterpret_cast<float4*>(dst + (long long)r * D64)[lane] = acc;
}

extern "C" void kernel_launch(void* const* d_in, const int* in_sizes, int n_in,
                              void* d_out, int out_size) {
    const float* user_emb = (const float*)d_in[0];
    const float* item_emb = (const float*)d_in[1];
    const int*   g_rows = (const int*)d_in[2];
    const int*   g_cols = (const int*)d_in[3];
    const float* g_vals = (const float*)d_in[4];
    const int*   u_rows = (const int*)d_in[5];
    const int*   u_cols = (const int*)d_in[6];
    const float* u_vals = (const float*)d_in[7];
    const int*   i_rows = (const int*)d_in[8];
    const int*   i_cols = (const int*)d_in[9];
    const float* i_vals = (const float*)d_in[10];

    float* out = (float*)d_out;

    const int U_ = in_sizes[0] / D64;   // 100000
    const int I_ = in_sizes[1] / D64;   // 50000
    const int N_ = U_ + I_;
    const int EG = in_sizes[2];
    const int EU = in_sizes[5];
    const int EI = in_sizes[8];
    const int ET = EG + EU + EI;

    // Zero the histogram counters.
    void* counts_ptr = nullptr;
    cudaGetSymbolAddress(&counts_ptr, d_counts);
    cudaMemsetAsync(counts_ptr, 0, (size_t)(N_ + U_ + I_) * sizeof(int), 0);

    // Build: histogram -> scan -> scatter.
    {
        int blocks = (ET + TPB - 1) / TPB;
        hist_all<<<blocks, TPB>>>(g_rows, u_rows, i_rows, EG, EU, EI, N_, U_);
    }
    scan_seg<<<3, 1024>>>(N_, U_, I_);
    {
        int blocks = (ET + TPB - 1) / TPB;
        scatter_all<<<blocks, TPB>>>(g_rows, g_cols, g_vals,
                                     u_rows, u_cols, u_vals,
                                     i_rows, i_cols, i_vals,
                                     EG, EU, EI, N_, U_);
    }

    // Main SpMMs (register accumulation, plain stores, no memset of d_out needed).
    float* dst_graph = out;                               // all_emb1
    float* dst_user2 = out + (long long)N_ * D64;         // user_emb2
    float* dst_item2 = out + (long long)(N_ + U_) * D64;  // item_emb2

    {
        int threads = N_ * 16;
        csr_spmm<<<(threads + TPB - 1) / TPB, TPB>>>(user_emb, item_emb, dst_graph,
                                                     N_, U_, 0, 0);
    }
    {
        int threads = U_ * 16;
        csr_spmm<<<(threads + TPB - 1) / TPB, TPB>>>(user_emb, user_emb, dst_user2,
                                                     U_, 0x7FFFFFFF, N_, EG);
    }
    {
        int threads = I_ * 16;
        csr_spmm<<<(threads + TPB - 1) / TPB, TPB>>>(item_emb, item_emb, dst_item2,
                                                     I_, 0x7FFFFFFF, N_ + U_, EG + EU);
    }
}

// round 5
// speedup vs baseline: 2.1440x; 2.1440x over previous
#include <cuda_runtime.h>
#include <cstdint>

// Problem constants (fixed by dataset).
#define U_C  100000
#define I_C  50000
#define N_C  150000
#define ROWS_TOT (N_C + U_C + I_C)       // 300000
#define CAP  64                          // bucket capacity (Poisson(16) tail ~0; spill list for exactness)

#define TPB 256
#define D64 64

// Output layout (fp32): out row index == key for every segment:
//   graph key r      -> out row r          (all_emb1, rows [0,N))
//   user  key N+r    -> out row N+r        (user_emb2)
//   item  key N+U+r  -> out row N+U+r      (item_emb2)

// Scratch (static device globals; no runtime allocation).
__device__ int  d_curs[ROWS_TOT];
__device__ int2 d_perm[(size_t)ROWS_TOT * CAP];   // {col, val_bits}, bucket = key*CAP
__device__ int  d_ovf_count;
__device__ int4 d_ovf[65536];                     // {key, col, val_bits, 0}

// ---------------- build: single scatter pass ----------------
__global__ void __launch_bounds__(TPB) scatter_all(
        const int* __restrict__ gr, const int* __restrict__ gc, const float* __restrict__ gv,
        const int* __restrict__ ur, const int* __restrict__ uc, const float* __restrict__ uv,
        const int* __restrict__ ir, const int* __restrict__ ic, const float* __restrict__ iv,
        int EG, int EU, int EI, int N_, int U_) {
    int e = blockIdx.x * TPB + threadIdx.x;
    int ET = EG + EU + EI;
    if (e >= ET) return;

    int key, c; float v;
    if (e < EG) {
        key = gr[e];            c = gc[e];  v = gv[e];
    } else if (e < EG + EU) {
        int k = e - EG;
        key = N_ + ur[k];       c = uc[k];  v = uv[k];
    } else {
        int k = e - EG - EU;
        key = N_ + U_ + ir[k];  c = ic[k];  v = iv[k];
    }

    int pos = atomicAdd(&d_curs[key], 1);
    if (pos < CAP) {
        d_perm[(size_t)key * CAP + pos] = make_int2(c, __float_as_int(v));
    } else {
        int o = atomicAdd(&d_ovf_count, 1);
        if (o < 65536) d_ovf[o] = make_int4(key, c, __float_as_int(v), 0);
    }
}

// ---------------- main CSR SpMM ----------------
// 16 threads per destination row; register accumulation; one STG.128 per slice.
__global__ void __launch_bounds__(TPB) csr_spmm(const float* __restrict__ src0,
                                                const float* __restrict__ src1,
                                                float* __restrict__ dst,
                                                int n_rows, int U_split, int row_base) {
    int tid  = blockIdx.x * TPB + threadIdx.x;
    int r    = tid >> 4;
    int lane = tid & 15;
    if (r >= n_rows) return;

    int key = row_base + r;
    int deg = min(d_curs[key], CAP);
    const int2* bucket = d_perm + (size_t)key * CAP;

    float4 acc = make_float4(0.f, 0.f, 0.f, 0.f);

    int j = 0;
    for (; j + 4 <= deg; j += 4) {
        int2 e0 = bucket[j];
        int2 e1 = bucket[j + 1];
        int2 e2 = bucket[j + 2];
        int2 e3 = bucket[j + 3];
        const float* p0 = (e0.x < U_split) ? src0 + (long long)e0.x * D64 : src1 + (long long)(e0.x - U_split) * D64;
        const float* p1 = (e1.x < U_split) ? src0 + (long long)e1.x * D64 : src1 + (long long)(e1.x - U_split) * D64;
        const float* p2 = (e2.x < U_split) ? src0 + (long long)e2.x * D64 : src1 + (long long)(e2.x - U_split) * D64;
        const float* p3 = (e3.x < U_split) ? src0 + (long long)e3.x * D64 : src1 + (long long)(e3.x - U_split) * D64;
        float4 x0 = reinterpret_cast<const float4*>(p0)[lane];
        float4 x1 = reinterpret_cast<const float4*>(p1)[lane];
        float4 x2 = reinterpret_cast<const float4*>(p2)[lane];
        float4 x3 = reinterpret_cast<const float4*>(p3)[lane];
        float v0 = __int_as_float(e0.y), v1 = __int_as_float(e1.y);
        float v2 = __int_as_float(e2.y), v3 = __int_as_float(e3.y);
        acc.x = fmaf(v0, x0.x, acc.x); acc.y = fmaf(v0, x0.y, acc.y); acc.z = fmaf(v0, x0.z, acc.z); acc.w = fmaf(v0, x0.w, acc.w);
        acc.x = fmaf(v1, x1.x, acc.x); acc.y = fmaf(v1, x1.y, acc.y); acc.z = fmaf(v1, x1.z, acc.z); acc.w = fmaf(v1, x1.w, acc.w);
        acc.x = fmaf(v2, x2.x, acc.x); acc.y = fmaf(v2, x2.y, acc.y); acc.z = fmaf(v2, x2.z, acc.z); acc.w = fmaf(v2, x2.w, acc.w);
        acc.x = fmaf(v3, x3.x, acc.x); acc.y = fmaf(v3, x3.y, acc.y); acc.z = fmaf(v3, x3.z, acc.z); acc.w = fmaf(v3, x3.w, acc.w);
    }
    for (; j < deg; j++) {
        int2 e = bucket[j];
        const float* p = (e.x < U_split) ? src0 + (long long)e.x * D64 : src1 + (long long)(e.x - U_split) * D64;
        float4 x = reinterpret_cast<const float4*>(p)[lane];
        float v = __int_as_float(e.y);
        acc.x = fmaf(v, x.x, acc.x); acc.y = fmaf(v, x.y, acc.y);
        acc.z = fmaf(v, x.z, acc.z); acc.w = fmaf(v, x.w, acc.w);
    }

    reinterpret_cast<float4*>(dst + (long long)r * D64)[lane] = acc;
}

// ---------------- overflow fixup (exactness; expected n==0) ----------------
__global__ void __launch_bounds__(TPB) fixup(const float* __restrict__ user_emb,
                                             const float* __restrict__ item_emb,
                                             float* __restrict__ out,
                                             int N_, int U_) {
    int n = min(d_ovf_count, 65536);
    long long total = (long long)n * 16;
    for (long long t = blockIdx.x * (long long)TPB + threadIdx.x; t < total;
         t += (long long)gridDim.x * TPB) {
        int idx  = (int)(t >> 4);
        int lane = (int)(t & 15);
        int4 e = d_ovf[idx];
        int key = e.x, c = e.y;
        float v = __int_as_float(e.z);
        const float* src;
        if (key < N_)            src = (c < U_) ? user_emb + (long long)c * D64
                                                : item_emb + (long long)(c - U_) * D64;
        else if (key < N_ + U_)  src = user_emb + (long long)c * D64;
        else                     src = item_emb + (long long)c * D64;
        float4 x = reinterpret_cast<const float4*>(src)[lane];
        x.x *= v; x.y *= v; x.z *= v; x.w *= v;
        float4* d = reinterpret_cast<float4*>(out + (long long)key * D64) + lane;
        asm volatile("red.global.add.v4.f32 [%0], {%1,%2,%3,%4};"
                     :: "l"(d), "f"(x.x), "f"(x.y), "f"(x.z), "f"(x.w)
                     : "memory");
    }
}

extern "C" void kernel_launch(void* const* d_in, const int* in_sizes, int n_in,
                              void* d_out, int out_size) {
    const float* user_emb = (const float*)d_in[0];
    const float* item_emb = (const float*)d_in[1];
    const int*   g_rows = (const int*)d_in[2];
    const int*   g_cols = (const int*)d_in[3];
    const float* g_vals = (const float*)d_in[4];
    const int*   u_rows = (const int*)d_in[5];
    const int*   u_cols = (const int*)d_in[6];
    const float* u_vals = (const float*)d_in[7];
    const int*   i_rows = (const int*)d_in[8];
    const int*   i_cols = (const int*)d_in[9];
    const float* i_vals = (const float*)d_in[10];

    float* out = (float*)d_out;

    const int U_ = in_sizes[0] / D64;   // 100000
    const int I_ = in_sizes[1] / D64;   // 50000
    const int N_ = U_ + I_;
    const int EG = in_sizes[2];
    const int EU = in_sizes[5];
    const int EI = in_sizes[8];
    const int ET = EG + EU + EI;

    // Zero cursors + overflow counter.
    void* curs_ptr = nullptr;
    cudaGetSymbolAddress(&curs_ptr, d_curs);
    cudaMemsetAsync(curs_ptr, 0, (size_t)(N_ + U_ + I_) * sizeof(int), 0);
    void* ovf_ptr = nullptr;
    cudaGetSymbolAddress(&ovf_ptr, d_ovf_count);
    cudaMemsetAsync(ovf_ptr, 0, sizeof(int), 0);

    // Build: single bucket-scatter pass.
    scatter_all<<<(ET + TPB - 1) / TPB, TPB>>>(g_rows, g_cols, g_vals,
                                               u_rows, u_cols, u_vals,
                                               i_rows, i_cols, i_vals,
                                               EG, EU, EI, N_, U_);

    // Mains: register accumulation, one plain store per row slice.
    float* dst_graph = out;
    float* dst_user2 = out + (long long)N_ * D64;
    float* dst_item2 = out + (long long)(N_ + U_) * D64;

    csr_spmm<<<(N_ * 16 + TPB - 1) / TPB, TPB>>>(user_emb, item_emb, dst_graph,
                                                 N_, U_, 0);
    csr_spmm<<<(U_ * 16 + TPB - 1) / TPB, TPB>>>(user_emb, user_emb, dst_user2,
                                                 U_, 0x7FFFFFFF, N_);
    csr_spmm<<<(I_ * 16 + TPB - 1) / TPB, TPB>>>(item_emb, item_emb, dst_item2,
                                                 I_, 0x7FFFFFFF, N_ + U_);

    // Exactness fixup for any bucket overflow (expected zero work).
    fixup<<<32, TPB>>>(user_emb, item_emb, out, N_, U_);
}

// round 6
// speedup vs baseline: 2.2951x; 1.0705x over previous
#include <cuda_runtime.h>
#include <cstdint>

// Problem constants (fixed by dataset).
#define U_C  100000
#define I_C  50000
#define N_C  150000
#define ROWS_TOT (N_C + U_C + I_C)       // 300000
#define CAP  24                          // bucket capacity; perm = 57.6MB -> L2-resident
#define OVF_CAP 65536

#define TPB 256
#define D64 64

// Output layout (fp32): out row index == key for every segment:
//   graph key r     -> out row r          (all_emb1 rows [0,N))
//   user  key N+r   -> out row N+r        (user_emb2)
//   item  key N+U+r -> out row N+U+r      (item_emb2)

__device__ int  d_curs[ROWS_TOT];
__device__ int2 d_perm[(size_t)ROWS_TOT * CAP];
__device__ int  d_ovf_count;
__device__ int4 d_ovf[OVF_CAP];          // {key, col, val_bits, 0}

// ---------------- build: single bucket-scatter pass ----------------
__global__ void __launch_bounds__(TPB) scatter_all(
        const int* __restrict__ gr, const int* __restrict__ gc, const float* __restrict__ gv,
        const int* __restrict__ ur, const int* __restrict__ uc, const float* __restrict__ uv,
        const int* __restrict__ ir, const int* __restrict__ ic, const float* __restrict__ iv,
        int EG, int EU, int EI, int N_, int U_) {
    int e = blockIdx.x * TPB + threadIdx.x;
    int ET = EG + EU + EI;
    if (e >= ET) return;

    int key, c; float v;
    if (e < EG) {
        key = __ldcs(gr + e);           c = __ldcs(gc + e);  v = __ldcs(gv + e);
    } else if (e < EG + EU) {
        int k = e - EG;
        key = N_ + __ldcs(ur + k);      c = __ldcs(uc + k);  v = __ldcs(uv + k);
    } else {
        int k = e - EG - EU;
        key = N_ + U_ + __ldcs(ir + k); c = __ldcs(ic + k);  v = __ldcs(iv + k);
    }

    int pos = atomicAdd(&d_curs[key], 1);
    if (pos < CAP) {
        d_perm[(size_t)key * CAP + pos] = make_int2(c, __float_as_int(v));
    } else {
        int o = atomicAdd(&d_ovf_count, 1);
        if (o < OVF_CAP) d_ovf[o] = make_int4(key, c, __float_as_int(v), 0);
    }
}

// ---------------- fused main: all 300K rows in one launch ----------------
// 16 threads per destination row; register accumulation; one streaming
// STG.128 per row slice. Per-row segment dispatch picks src tables.
__global__ void __launch_bounds__(TPB) csr_spmm_fused(const float* __restrict__ user_emb,
                                                      const float* __restrict__ item_emb,
                                                      float* __restrict__ out,
                                                      int N_, int U_, int I_) {
    int tid  = blockIdx.x * TPB + threadIdx.x;
    int key  = tid >> 4;
    int lane = tid & 15;
    if (key >= N_ + U_ + I_) return;

    const float* src0;
    const float* src1;
    int U_split;
    if (key < N_) {                    // graph: concat(user, item) source
        src0 = user_emb; src1 = item_emb; U_split = U_;
    } else if (key < N_ + U_) {        // user SpMM
        src0 = user_emb; src1 = user_emb; U_split = 0x7FFFFFFF;
    } else {                           // item SpMM
        src0 = item_emb; src1 = item_emb; U_split = 0x7FFFFFFF;
    }

    int deg = min(d_curs[key], CAP);
    const int2* bucket = d_perm + (size_t)key * CAP;

    float4 acc = make_float4(0.f, 0.f, 0.f, 0.f);

    int j = 0;
    for (; j + 4 <= deg; j += 4) {
        int2 e0 = __ldcs(bucket + j);
        int2 e1 = __ldcs(bucket + j + 1);
        int2 e2 = __ldcs(bucket + j + 2);
        int2 e3 = __ldcs(bucket + j + 3);
        const float* p0 = (e0.x < U_split) ? src0 + (long long)e0.x * D64 : src1 + (long long)(e0.x - U_split) * D64;
        const float* p1 = (e1.x < U_split) ? src0 + (long long)e1.x * D64 : src1 + (long long)(e1.x - U_split) * D64;
        const float* p2 = (e2.x < U_split) ? src0 + (long long)e2.x * D64 : src1 + (long long)(e2.x - U_split) * D64;
        const float* p3 = (e3.x < U_split) ? src0 + (long long)e3.x * D64 : src1 + (long long)(e3.x - U_split) * D64;
        float4 x0 = reinterpret_cast<const float4*>(p0)[lane];
        float4 x1 = reinterpret_cast<const float4*>(p1)[lane];
        float4 x2 = reinterpret_cast<const float4*>(p2)[lane];
        float4 x3 = reinterpret_cast<const float4*>(p3)[lane];
        float v0 = __int_as_float(e0.y), v1 = __int_as_float(e1.y);
        float v2 = __int_as_float(e2.y), v3 = __int_as_float(e3.y);
        acc.x = fmaf(v0, x0.x, acc.x); acc.y = fmaf(v0, x0.y, acc.y); acc.z = fmaf(v0, x0.z, acc.z); acc.w = fmaf(v0, x0.w, acc.w);
        acc.x = fmaf(v1, x1.x, acc.x); acc.y = fmaf(v1, x1.y, acc.y); acc.z = fmaf(v1, x1.z, acc.z); acc.w = fmaf(v1, x1.w, acc.w);
        acc.x = fmaf(v2, x2.x, acc.x); acc.y = fmaf(v2, x2.y, acc.y); acc.z = fmaf(v2, x2.z, acc.z); acc.w = fmaf(v2, x2.w, acc.w);
        acc.x = fmaf(v3, x3.x, acc.x); acc.y = fmaf(v3, x3.y, acc.y); acc.z = fmaf(v3, x3.z, acc.z); acc.w = fmaf(v3, x3.w, acc.w);
    }
    for (; j < deg; j++) {
        int2 e = __ldcs(bucket + j);
        const float* p = (e.x < U_split) ? src0 + (long long)e.x * D64 : src1 + (long long)(e.x - U_split) * D64;
        float4 x = reinterpret_cast<const float4*>(p)[lane];
        float v = __int_as_float(e.y);
        acc.x = fmaf(v, x.x, acc.x); acc.y = fmaf(v, x.y, acc.y);
        acc.z = fmaf(v, x.z, acc.z); acc.w = fmaf(v, x.w, acc.w);
    }

    // Streaming store: write-once, don't pollute L2.
    __stcs(reinterpret_cast<float4*>(out + (long long)key * D64) + lane, acc);
}

// ---------------- overflow fixup (exactness; ~8K edges expected) ----------------
__global__ void __launch_bounds__(TPB) fixup(const float* __restrict__ user_emb,
                                             const float* __restrict__ item_emb,
                                             float* __restrict__ out,
                                             int N_, int U_) {
    int n = min(d_ovf_count, OVF_CAP);
    long long total = (long long)n * 16;
    for (long long t = blockIdx.x * (long long)TPB + threadIdx.x; t < total;
         t += (long long)gridDim.x * TPB) {
        int idx  = (int)(t >> 4);
        int lane = (int)(t & 15);
        int4 e = d_ovf[idx];
        int key = e.x, c = e.y;
        float v = __int_as_float(e.z);
        const float* src;
        if (key < N_)            src = (c < U_) ? user_emb + (long long)c * D64
                                                : item_emb + (long long)(c - U_) * D64;
        else if (key < N_ + U_)  src = user_emb + (long long)c * D64;
        else                     src = item_emb + (long long)c * D64;
        float4 x = reinterpret_cast<const float4*>(src)[lane];
        x.x *= v; x.y *= v; x.z *= v; x.w *= v;
        float4* d = reinterpret_cast<float4*>(out + (long long)key * D64) + lane;
        asm volatile("red.global.add.v4.f32 [%0], {%1,%2,%3,%4};"
                     :: "l"(d), "f"(x.x), "f"(x.y), "f"(x.z), "f"(x.w)
                     : "memory");
    }
}

extern "C" void kernel_launch(void* const* d_in, const int* in_sizes, int n_in,
                              void* d_out, int out_size) {
    const float* user_emb = (const float*)d_in[0];
    const float* item_emb = (const float*)d_in[1];
    const int*   g_rows = (const int*)d_in[2];
    const int*   g_cols = (const int*)d_in[3];
    const float* g_vals = (const float*)d_in[4];
    const int*   u_rows = (const int*)d_in[5];
    const int*   u_cols = (const int*)d_in[6];
    const float* u_vals = (const float*)d_in[7];
    const int*   i_rows = (const int*)d_in[8];
    const int*   i_cols = (const int*)d_in[9];
    const float* i_vals = (const float*)d_in[10];

    float* out = (float*)d_out;

    const int U_ = in_sizes[0] / D64;   // 100000
    const int I_ = in_sizes[1] / D64;   // 50000
    const int N_ = U_ + I_;
    const int EG = in_sizes[2];
    const int EU = in_sizes[5];
    const int EI = in_sizes[8];
    const int ET = EG + EU + EI;
    const int ROWS = N_ + U_ + I_;

    // Zero cursors + overflow counter.
    void* curs_ptr = nullptr;
    cudaGetSymbolAddress(&curs_ptr, d_curs);
    cudaMemsetAsync(curs_ptr, 0, (size_t)ROWS * sizeof(int), 0);
    void* ovf_ptr = nullptr;
    cudaGetSymbolAddress(&ovf_ptr, d_ovf_count);
    cudaMemsetAsync(ovf_ptr, 0, sizeof(int), 0);

    // Build.
    scatter_all<<<(ET + TPB - 1) / TPB, TPB>>>(g_rows, g_cols, g_vals,
                                               u_rows, u_cols, u_vals,
                                               i_rows, i_cols, i_vals,
                                               EG, EU, EI, N_, U_);

    // Fused main over all rows.
    {
        long long threads = (long long)ROWS * 16;
        int blocks = (int)((threads + TPB - 1) / TPB);
        csr_spmm_fused<<<blocks, TPB>>>(user_emb, item_emb, out, N_, U_, I_);
    }

    // Exact fixup for bucket overflow.
    fixup<<<256, TPB>>>(user_emb, item_emb, out, N_, U_);
}